// round 7
// baseline (speedup 1.0000x reference)
#include <cuda_runtime.h>
#include <cstdint>

// image: [64, 3, 512, 512] fp32; mask [64,64] bool-as-int32 (rate ~0.5).
// out = where(mask8x8, -1.0f, image).
//
// R7: sector-aligned items. One mask element = 8 floats = 32B = 1 sector.
// Each thread-item = 2 adjacent float4s (32B) -> single mask lookup, and
// ptxas can fuse the adjacent 16B accesses into 256-bit LDG/STG on sm_103a.
// Predicated loads (skip masked sectors), __stcs stores, pinned L2 prefix.

#define W4 128            // float4s per row (W=512)
#define UNROLL 4          // 32B items per thread

__global__ void __launch_bounds__(256) grid_crop_kernel(
    const float4* __restrict__ img,
    const int* __restrict__ sw,      // [64,64] bool-as-int32
    float4* __restrict__ out,
    int pin_n4)
{
    // Each item = 2 consecutive float4s. Block covers 256*2*UNROLL = 2048 f4.
    int base2 = blockIdx.x * (256 * UNROLL) + threadIdx.x;  // item index

    int i0[UNROLL];
    int m[UNROLL];
    float4 a[UNROLL], b[UNROLL];

    #pragma unroll
    for (int k = 0; k < UNROLL; k++) {
        int item = base2 + k * 256;
        i0[k] = item * 2;                     // first float4 of the 32B item
        int w4 = i0[k] & (W4 - 1);            // even, 0..126
        int h  = (i0[k] >> 7) & 511;
        m[k] = __ldg(&sw[((h >> 3) << 6) | (w4 >> 1)]);
    }

    #pragma unroll
    for (int k = 0; k < UNROLL; k++) {
        a[k] = make_float4(-1.0f, -1.0f, -1.0f, -1.0f);
        b[k] = a[k];
        if (!m[k]) {
            if (i0[k] < pin_n4) {
                a[k] = __ldg(&img[i0[k]]);
                b[k] = __ldg(&img[i0[k] + 1]);
            } else {
                a[k] = __ldcs(&img[i0[k]]);
                b[k] = __ldcs(&img[i0[k] + 1]);
            }
        }
    }

    #pragma unroll
    for (int k = 0; k < UNROLL; k++) {
        __stcs(&out[i0[k]], a[k]);
        __stcs(&out[i0[k] + 1], b[k]);
    }
}

extern "C" void kernel_launch(void* const* d_in, const int* in_sizes, int n_in,
                              void* d_out, int out_size)
{
    const void* p_img = d_in[0];
    const void* p_sw  = d_in[1];
    if (n_in >= 2 && in_sizes[0] < in_sizes[1]) {
        p_img = d_in[1];
        p_sw  = d_in[0];
    }

    const float4* img = (const float4*)p_img;
    const int* sw = (const int*)p_sw;
    float4* out = (float4*)d_out;

    int n4 = out_size / 4;                      // 12,582,912
    int pin_n4 = n4 / 2;                        // first ~100MB default-cached
    int blocks = n4 / (256 * 2 * UNROLL);       // 6,144 exact
    grid_crop_kernel<<<blocks, 256>>>(img, sw, out, pin_n4);
}

// round 9
// speedup vs baseline: 1.0672x; 1.0672x over previous
#include <cuda_runtime.h>
#include <cstdint>

// image: [64, 3, 512, 512] fp32; mask [64,64] bool-as-int32 (rate ~0.5).
// out = where(mask8x8, -1.0f, image).
//
// Champion config (R4/R6) trimmed: UNROLL=4, sector-predicated loads
// (skip fully-masked 128B lines), __ldcg image loads (L2-only; each byte
// read once per launch so L1 allocation is wasted work), __stcs stores.

#define W4 128            // float4s per row (W=512)
#define UNROLL 4

__global__ void __launch_bounds__(256) grid_crop_kernel(
    const float4* __restrict__ img,
    const int* __restrict__ sw,      // [64,64] bool-as-int32
    float4* __restrict__ out)
{
    int base = blockIdx.x * (256 * UNROLL) + threadIdx.x;

    int idx[UNROLL];
    int m[UNROLL];
    float4 v[UNROLL];

    // Mask lookups (L1-resident, broadcast across 8 adjacent threads).
    #pragma unroll
    for (int k = 0; k < UNROLL; k++) {
        idx[k] = base + k * 256;
        int w4 = idx[k] & (W4 - 1);          // 0..127
        int h  = (idx[k] >> 7) & 511;        // 0..511
        m[k] = __ldg(&sw[((h >> 3) << 6) | (w4 >> 1)]);
    }

    // Predicated L2-only loads: masked sectors never fetched; no L1 alloc.
    #pragma unroll
    for (int k = 0; k < UNROLL; k++) {
        v[k] = make_float4(-1.0f, -1.0f, -1.0f, -1.0f);
        if (!m[k]) v[k] = __ldcg(&img[idx[k]]);
    }

    // Evict-first streaming stores.
    #pragma unroll
    for (int k = 0; k < UNROLL; k++) {
        __stcs(&out[idx[k]], v[k]);
    }
}

extern "C" void kernel_launch(void* const* d_in, const int* in_sizes, int n_in,
                              void* d_out, int out_size)
{
    const void* p_img = d_in[0];
    const void* p_sw  = d_in[1];
    if (n_in >= 2 && in_sizes[0] < in_sizes[1]) {
        p_img = d_in[1];
        p_sw  = d_in[0];
    }

    const float4* img = (const float4*)p_img;
    const int* sw = (const int*)p_sw;
    float4* out = (float4*)d_out;

    int n4 = out_size / 4;                      // 12,582,912
    int blocks = n4 / (256 * UNROLL);           // 12,288 exact
    grid_crop_kernel<<<blocks, 256>>>(img, sw, out);
}